// round 11
// baseline (speedup 1.0000x reference)
#include <cuda_runtime.h>
#include <cuda_bf16.h>
#include <cstdint>

// smem map (256B-stride XOR-swizzled rows):
//  XH/XL: X hi/lo, 256 rows
//  XWH/XWL: XW hi/lo, 128 rows (XWL holds W-lo during GEMM1)
//  PW: W-hi during GEMM1; then per-pair P chunk rows (16 rows/pair, [hi 128B | lo 128B])
#define XH_OFF 0
#define XL_OFF 65536
#define XWH_OFF 131072
#define XWL_OFF 163840
#define PW_OFF  196608
#define SUMA_OFF 229376
#define SUMM_OFF 230400
#define SMEM_TOTAL 231424

__device__ __forceinline__ uint32_t smem_u32(const void* p) {
    uint32_t a;
    asm("{ .reg .u64 t; cvta.to.shared.u64 t, %1; cvt.u32.u64 %0, t; }" : "=r"(a) : "l"(p));
    return a;
}
__device__ __forceinline__ uint32_t soff(uint32_t region, int row, int byte) {
    return region + (uint32_t)(row * 256 + (byte ^ ((row & 7) << 4)));
}
__device__ __forceinline__ void ldsm4(uint32_t addr, uint32_t (&r)[4]) {
    asm volatile("ldmatrix.sync.aligned.m8n8.x4.shared.b16 {%0,%1,%2,%3}, [%4];"
                 : "=r"(r[0]), "=r"(r[1]), "=r"(r[2]), "=r"(r[3]) : "r"(addr));
}
__device__ __forceinline__ void ldsm4t(uint32_t addr, uint32_t (&r)[4]) {
    asm volatile("ldmatrix.sync.aligned.m8n8.x4.trans.shared.b16 {%0,%1,%2,%3}, [%4];"
                 : "=r"(r[0]), "=r"(r[1]), "=r"(r[2]), "=r"(r[3]) : "r"(addr));
}
__device__ __forceinline__ void mma16816(float (&c)[4], const uint32_t (&a)[4],
                                         uint32_t b0, uint32_t b1) {
    asm volatile("mma.sync.aligned.m16n8k16.row.col.f32.bf16.bf16.f32 "
                 "{%0,%1,%2,%3}, {%4,%5,%6,%7}, {%8,%9}, {%0,%1,%2,%3};"
                 : "+f"(c[0]), "+f"(c[1]), "+f"(c[2]), "+f"(c[3])
                 : "r"(a[0]), "r"(a[1]), "r"(a[2]), "r"(a[3]), "r"(b0), "r"(b1));
}
__device__ __forceinline__ uint32_t bpack(float x, float y) {
    __nv_bfloat162 h = __floats2bfloat162_rn(x, y);
    return *reinterpret_cast<uint32_t*>(&h);
}
__device__ __forceinline__ uint32_t bpacklo(float x, float y) {
    float hx = __bfloat162float(__float2bfloat16_rn(x));
    float hy = __bfloat162float(__float2bfloat16_rn(y));
    return bpack(x - hx, y - hy);
}
#define BARP(id) asm volatile("bar.sync %0, %1;" :: "r"(id), "r"(64) : "memory")

__global__ void __launch_bounds__(512, 1)
sattn_mma_kernel(const float* __restrict__ words, const float* __restrict__ Wm,
                 const int* __restrict__ vlen, float* __restrict__ out)
{
    extern __shared__ __align__(1024) char smem[];
    const uint32_t sb = smem_u32(smem);
    const int tid = threadIdx.x, lane = tid & 31, warp = tid >> 5;
    const int pair = warp >> 1, side = warp & 1, barid = 1 + pair;
    const int sent = blockIdx.x >> 1, q0 = (blockIdx.x & 1) * 128;
    const float* xg = words + (size_t)sent * 256 * 128;
    const int len = vlen[sent];
    const int g = lane >> 2, q4 = lane & 3;
    const int qr = pair * 16;                 // CTA-local query-row base (16 rows/pair)

    // ---- load X -> XH/XL ----
    for (int i = tid; i < 8192; i += 512) {
        float4 v = ((const float4*)xg)[i];
        int t = i >> 5, b = (i & 31) << 3;
        uint2 hw, lw;
        hw.x = bpack(v.x, v.y); hw.y = bpack(v.z, v.w);
        lw.x = bpacklo(v.x, v.y); lw.y = bpacklo(v.z, v.w);
        *(uint2*)(smem + soff(XH_OFF, t, b)) = hw;
        *(uint2*)(smem + soff(XL_OFF, t, b)) = lw;
    }
    // ---- load W ([k][n]): hi -> PW region, lo -> XWL region ----
    for (int i = tid; i < 4096; i += 512) {
        float4 v = ((const float4*)Wm)[i];
        int k = i >> 5, b = (i & 31) << 3;
        uint2 hw, lw;
        hw.x = bpack(v.x, v.y); hw.y = bpack(v.z, v.w);
        lw.x = bpacklo(v.x, v.y); lw.y = bpacklo(v.z, v.w);
        *(uint2*)(smem + soff(PW_OFF, k, b)) = hw;
        *(uint2*)(smem + soff(XWL_OFF, k, b)) = lw;
    }
    __syncthreads();

    // ===== GEMM1: XW[16q x 64c(side)] = Xq @ W (3 passes, B loaded once/kt) =====
    {
        float xw[8][4];
        #pragma unroll
        for (int u = 0; u < 8; ++u) xw[u][0] = xw[u][1] = xw[u][2] = xw[u][3] = 0.f;

        #pragma unroll
        for (int kt = 0; kt < 8; ++kt) {
            uint32_t Ah[4], Al[4];
            {
                int row = q0 + qr + (lane & 15);
                int byt = kt * 32 + ((lane >> 4) << 4);
                ldsm4(sb + soff(XH_OFF, row, byt), Ah);
                ldsm4(sb + soff(XL_OFF, row, byt), Al);
            }
            const int rr = kt * 16 + (lane & 7) + (((lane >> 3) & 1) << 3);
            uint32_t Bh[4][4], Bl[4][4];
            #pragma unroll
            for (int nn = 0; nn < 4; ++nn) {
                int bb = ((side * 64 + nn * 16) + ((lane >> 4) << 3)) * 2;
                ldsm4t(sb + soff(PW_OFF, rr, bb), Bh[nn]);
                ldsm4t(sb + soff(XWL_OFF, rr, bb), Bl[nn]);
            }
            #pragma unroll
            for (int nn = 0; nn < 4; ++nn) {
                mma16816(xw[2 * nn],     Ah, Bh[nn][0], Bh[nn][1]);
                mma16816(xw[2 * nn + 1], Ah, Bh[nn][2], Bh[nn][3]);
            }
            #pragma unroll
            for (int nn = 0; nn < 4; ++nn) {
                mma16816(xw[2 * nn],     Al, Bh[nn][0], Bh[nn][1]);
                mma16816(xw[2 * nn + 1], Al, Bh[nn][2], Bh[nn][3]);
            }
            #pragma unroll
            for (int nn = 0; nn < 4; ++nn) {
                mma16816(xw[2 * nn],     Ah, Bl[nn][0], Bl[nn][1]);
                mma16816(xw[2 * nn + 1], Ah, Bl[nn][2], Bl[nn][3]);
            }
        }
        __syncthreads();   // all warps done reading W-hi/W-lo

        // store XW hi/lo (own 64-col slice) into XWH/XWL
        #pragma unroll
        for (int u = 0; u < 8; ++u) {
            int nbyte = 2 * (side * 64 + 8 * u + 2 * q4);
            int rA = qr + g, rB = rA + 8;
            *(uint32_t*)(smem + soff(XWH_OFF, rA, nbyte)) = bpack(xw[u][0], xw[u][1]);
            *(uint32_t*)(smem + soff(XWL_OFF, rA, nbyte)) = bpacklo(xw[u][0], xw[u][1]);
            *(uint32_t*)(smem + soff(XWH_OFF, rB, nbyte)) = bpack(xw[u][2], xw[u][3]);
            *(uint32_t*)(smem + soff(XWL_OFF, rB, nbyte)) = bpacklo(xw[u][2], xw[u][3]);
        }
        __syncthreads();   // full XW visible; PW region free for P
    }

    // ===== per 32-key slice (own side) then pair-shared GEMM3 over 64 keys =====
    float oa[8][4];
    #pragma unroll
    for (int u = 0; u < 8; ++u) oa[u][0] = oa[u][1] = oa[u][2] = oa[u][3] = 0.f;
    float sa[2] = {0.f, 0.f}, sm_[2] = {0.f, 0.f};

    #pragma unroll 1
    for (int c = 0; c < 4; ++c) {
        const int kb = side * 128 + c * 32;   // this warp's 32 keys this step
        float la[4][4];
        #pragma unroll
        for (int u = 0; u < 4; ++u) la[u][0] = la[u][1] = la[u][2] = la[u][3] = 0.f;

        // ---- GEMM2: L[16q x 32k] = XW @ X[kb..kb+32]^T ----
        #pragma unroll
        for (int kt = 0; kt < 8; ++kt) {
            uint32_t Ah[4], Al[4];
            {
                int row = qr + (lane & 15);
                int byt = kt * 32 + ((lane >> 4) << 4);
                ldsm4(sb + soff(XWH_OFF, row, byt), Ah);
                ldsm4(sb + soff(XWL_OFF, row, byt), Al);
            }
            uint32_t Bh[2][4], Bl[2][4];
            #pragma unroll
            for (int nb = 0; nb < 2; ++nb) {
                int rr = kb + nb * 16 + (lane & 7) + ((lane >> 4) << 3);
                int bb = kt * 32 + (((lane >> 3) & 1) << 4);
                ldsm4(sb + soff(XH_OFF, rr, bb), Bh[nb]);
                ldsm4(sb + soff(XL_OFF, rr, bb), Bl[nb]);
            }
            #pragma unroll
            for (int nb = 0; nb < 2; ++nb) {
                mma16816(la[2 * nb],     Ah, Bh[nb][0], Bh[nb][1]);
                mma16816(la[2 * nb + 1], Ah, Bh[nb][2], Bh[nb][3]);
            }
            #pragma unroll
            for (int nb = 0; nb < 2; ++nb) {
                mma16816(la[2 * nb],     Ah, Bl[nb][0], Bl[nb][1]);
                mma16816(la[2 * nb + 1], Ah, Bl[nb][2], Bl[nb][3]);
            }
            #pragma unroll
            for (int nb = 0; nb < 2; ++nb) {
                mma16816(la[2 * nb],     Al, Bh[nb][0], Bh[nb][1]);
                mma16816(la[2 * nb + 1], Al, Bh[nb][2], Bh[nb][3]);
            }
        }

        // ---- tanh -> exp -> mask; write unnormalized P (bf16 hi/lo) to smem ----
        #pragma unroll
        for (int u = 0; u < 4; ++u) {          // u = nb*2 + hh, keys kb + u*8 + ...
            int tb = kb + u * 8 + 2 * q4;
            #pragma unroll
            for (int ch = 0; ch < 2; ++ch) {
                const bool m = (tb + ch) < len;
                {
                    float l = la[u][ch];
                    float e2 = __expf(2.f * l);
                    float th = 1.f - __fdividef(2.f, e2 + 1.f);
                    float w = __expf(th);
                    float wm = m ? w : 0.f;
                    sa[0] += w; sm_[0] += wm; la[u][ch] = wm;
                }
                {
                    float l = la[u][2 + ch];
                    float e2 = __expf(2.f * l);
                    float th = 1.f - __fdividef(2.f, e2 + 1.f);
                    float w = __expf(th);
                    float wm = m ? w : 0.f;
                    sa[1] += w; sm_[1] += wm; la[u][2 + ch] = wm;
                }
            }
        }
        #pragma unroll
        for (int u = 0; u < 4; ++u) {
            int pb = 2 * (side * 32 + u * 8 + 2 * q4);
            int rA = qr + g, rB = rA + 8;
            *(uint32_t*)(smem + soff(PW_OFF, rA, pb))       = bpack(la[u][0], la[u][1]);
            *(uint32_t*)(smem + soff(PW_OFF, rA, 128 + pb)) = bpacklo(la[u][0], la[u][1]);
            *(uint32_t*)(smem + soff(PW_OFF, rB, pb))       = bpack(la[u][2], la[u][3]);
            *(uint32_t*)(smem + soff(PW_OFF, rB, 128 + pb)) = bpacklo(la[u][2], la[u][3]);
        }
        BARP(barid);

        // ---- GEMM3: oa += P[16q x 64k] @ X[gk, side 64 cols] ----
        #pragma unroll
        for (int kt2 = 0; kt2 < 4; ++kt2) {
            uint32_t Ph[4], Pl[4];
            {
                int row = qr + (lane & 15);
                int byt = kt2 * 32 + ((lane >> 4) << 4);
                ldsm4(sb + soff(PW_OFF, row, byt), Ph);
                ldsm4(sb + soff(PW_OFF, row, 128 + byt), Pl);
            }
            const int gk = ((kt2 >> 1) * 128) + c * 32 + ((kt2 & 1) * 16);
            const int rr = gk + (lane & 7) + (((lane >> 3) & 1) << 3);
            uint32_t Bh[4][4], Bl[4][4];
            #pragma unroll
            for (int nn = 0; nn < 4; ++nn) {
                int bb = ((side * 64 + nn * 16) + ((lane >> 4) << 3)) * 2;
                ldsm4t(sb + soff(XH_OFF, rr, bb), Bh[nn]);
                ldsm4t(sb + soff(XL_OFF, rr, bb), Bl[nn]);
            }
            #pragma unroll
            for (int nn = 0; nn < 4; ++nn) {
                mma16816(oa[2 * nn],     Ph, Bh[nn][0], Bh[nn][1]);
                mma16816(oa[2 * nn + 1], Ph, Bh[nn][2], Bh[nn][3]);
            }
            #pragma unroll
            for (int nn = 0; nn < 4; ++nn) {
                mma16816(oa[2 * nn],     Ph, Bl[nn][0], Bl[nn][1]);
                mma16816(oa[2 * nn + 1], Ph, Bl[nn][2], Bl[nn][3]);
            }
            #pragma unroll
            for (int nn = 0; nn < 4; ++nn) {
                mma16816(oa[2 * nn],     Pl, Bh[nn][0], Bh[nn][1]);
                mma16816(oa[2 * nn + 1], Pl, Bh[nn][2], Bh[nn][3]);
            }
        }
        BARP(barid);   // P chunk consumed; safe to overwrite next step
    }

    // ===== sums: quad-reduce, exchange across pair, normalize, store =====
    #pragma unroll
    for (int off = 1; off <= 2; off <<= 1)
        #pragma unroll
        for (int rs = 0; rs < 2; ++rs) {
            sa[rs]  += __shfl_xor_sync(0xffffffffu, sa[rs],  off);
            sm_[rs] += __shfl_xor_sync(0xffffffffu, sm_[rs], off);
        }
    if (q4 == 0) {
        #pragma unroll
        for (int rs = 0; rs < 2; ++rs) {
            int idx = warp * 16 + rs * 8 + g;
            *(float*)(smem + SUMA_OFF + idx * 4) = sa[rs];
            *(float*)(smem + SUMM_OFF + idx * 4) = sm_[rs];
        }
    }
    BARP(barid);

    float inv[2];
    #pragma unroll
    for (int rs = 0; rs < 2; ++rs) {
        int i0 = warp * 16 + rs * 8 + g;
        int i1 = (warp ^ 1) * 16 + rs * 8 + g;
        float A = *(float*)(smem + SUMA_OFF + i0 * 4) + *(float*)(smem + SUMA_OFF + i1 * 4);
        float M = *(float*)(smem + SUMM_OFF + i0 * 4) + *(float*)(smem + SUMM_OFF + i1 * 4);
        inv[rs] = 1.f / (M + 1e-8f * A);
    }

    {
        const size_t rbase = (size_t)sent * 256 + q0 + qr;
        #pragma unroll
        for (int u = 0; u < 8; ++u) {          // u = nn*2 + hh
            int col = side * 64 + (u >> 1) * 16 + (u & 1) * 8 + 2 * q4;
            float2 v0, v1;
            v0.x = oa[u][0] * inv[0]; v0.y = oa[u][1] * inv[0];
            v1.x = oa[u][2] * inv[1]; v1.y = oa[u][3] * inv[1];
            *(float2*)(out + (rbase + g) * 128 + col) = v0;
            *(float2*)(out + (rbase + g + 8) * 128 + col) = v1;
        }
    }
}

extern "C" void kernel_launch(void* const* d_in, const int* in_sizes, int n_in,
                              void* d_out, int out_size)
{
    const float* words = (const float*)d_in[0];
    const float* Wm    = (const float*)d_in[1];
    const int*   vlen  = (const int*)d_in[2];
    float* out = (float*)d_out;

    cudaFuncSetAttribute(sattn_mma_kernel,
                         cudaFuncAttributeMaxDynamicSharedMemorySize, SMEM_TOTAL);
    sattn_mma_kernel<<<1024, 512, SMEM_TOTAL>>>(words, Wm, vlen, out);
}

// round 12
// speedup vs baseline: 1.3087x; 1.3087x over previous
#include <cuda_runtime.h>
#include <cuda_bf16.h>
#include <cstdint>

// smem: X hi/lo = 256x128 bf16 (row stride 256B, XOR-swizzled). W hi/lo = 128x128 bf16
// ([k][n]); after GEMM1 the W region is reused as XW hi/lo.
#define XH_OFF 0
#define XL_OFF 65536
#define WH_OFF 131072
#define WL_OFF 163840
#define SMEM_TOTAL 196608

__device__ __forceinline__ uint32_t smem_u32(const void* p) {
    uint32_t a;
    asm("{ .reg .u64 t; cvta.to.shared.u64 t, %1; cvt.u32.u64 %0, t; }" : "=r"(a) : "l"(p));
    return a;
}
__device__ __forceinline__ uint32_t soff(uint32_t region, int row, int byte) {
    return region + (uint32_t)(row * 256 + (byte ^ ((row & 7) << 4)));
}
__device__ __forceinline__ void ldsm4(uint32_t addr, uint32_t (&r)[4]) {
    asm volatile("ldmatrix.sync.aligned.m8n8.x4.shared.b16 {%0,%1,%2,%3}, [%4];"
                 : "=r"(r[0]), "=r"(r[1]), "=r"(r[2]), "=r"(r[3]) : "r"(addr));
}
__device__ __forceinline__ void ldsm4t(uint32_t addr, uint32_t (&r)[4]) {
    asm volatile("ldmatrix.sync.aligned.m8n8.x4.trans.shared.b16 {%0,%1,%2,%3}, [%4];"
                 : "=r"(r[0]), "=r"(r[1]), "=r"(r[2]), "=r"(r[3]) : "r"(addr));
}
__device__ __forceinline__ void mma16816(float (&c)[4], const uint32_t (&a)[4],
                                         uint32_t b0, uint32_t b1) {
    asm volatile("mma.sync.aligned.m16n8k16.row.col.f32.bf16.bf16.f32 "
                 "{%0,%1,%2,%3}, {%4,%5,%6,%7}, {%8,%9}, {%0,%1,%2,%3};"
                 : "+f"(c[0]), "+f"(c[1]), "+f"(c[2]), "+f"(c[3])
                 : "r"(a[0]), "r"(a[1]), "r"(a[2]), "r"(a[3]), "r"(b0), "r"(b1));
}
__device__ __forceinline__ uint32_t bpack(float x, float y) {
    __nv_bfloat162 h = __floats2bfloat162_rn(x, y);
    return *reinterpret_cast<uint32_t*>(&h);
}
__device__ __forceinline__ uint32_t bpacklo(float x, float y) {
    float hx = __bfloat162float(__float2bfloat16_rn(x));
    float hy = __bfloat162float(__float2bfloat16_rn(y));
    return bpack(x - hx, y - hy);
}

__global__ void __launch_bounds__(256, 1)
sattn_mma_kernel(const float* __restrict__ words, const float* __restrict__ Wm,
                 const int* __restrict__ vlen, float* __restrict__ out)
{
    extern __shared__ __align__(1024) char smem[];
    const uint32_t sb = smem_u32(smem);
    const int tid = threadIdx.x, lane = tid & 31, warp = tid >> 5;
    const int sent = blockIdx.x >> 1, q0 = (blockIdx.x & 1) * 128;
    const float* xg = words + (size_t)sent * 256 * 128;
    const int len = vlen[sent];
    const int g = lane >> 2, q4 = lane & 3;

    // ---- load X -> XH/XL ----
    for (int i = tid; i < 8192; i += 256) {
        float4 v = ((const float4*)xg)[i];
        int t = i >> 5, b = (i & 31) << 3;
        uint2 hw, lw;
        hw.x = bpack(v.x, v.y); hw.y = bpack(v.z, v.w);
        lw.x = bpacklo(v.x, v.y); lw.y = bpacklo(v.z, v.w);
        *(uint2*)(smem + soff(XH_OFF, t, b)) = hw;
        *(uint2*)(smem + soff(XL_OFF, t, b)) = lw;
    }
    // ---- load W ([k][n]) -> WH/WL ----
    for (int i = tid; i < 4096; i += 256) {
        float4 v = ((const float4*)Wm)[i];
        int k = i >> 5, b = (i & 31) << 3;
        uint2 hw, lw;
        hw.x = bpack(v.x, v.y); hw.y = bpack(v.z, v.w);
        lw.x = bpacklo(v.x, v.y); lw.y = bpacklo(v.z, v.w);
        *(uint2*)(smem + soff(WH_OFF, k, b)) = hw;
        *(uint2*)(smem + soff(WL_OFF, k, b)) = lw;
    }
    __syncthreads();

    const int r0 = q0 + warp * 16;

    // ===== GEMM1: XW[16 x 128] = Xq @ W (3-pass split) =====
    {
        float xw[16][4];
        #pragma unroll
        for (int j = 0; j < 16; ++j) { xw[j][0] = xw[j][1] = xw[j][2] = xw[j][3] = 0.f; }

        #pragma unroll
        for (int kt = 0; kt < 8; ++kt) {
            uint32_t Ah[4], Al[4];
            {
                int row = r0 + (lane & 15);
                int byt = kt * 32 + ((lane >> 4) << 4);
                ldsm4(sb + soff(XH_OFF, row, byt), Ah);
                ldsm4(sb + soff(XL_OFF, row, byt), Al);
            }
            #pragma unroll
            for (int nn = 0; nn < 8; ++nn) {
                uint32_t Bh[4], Bl[4];
                int rr = kt * 16 + (lane & 7) + (((lane >> 3) & 1) << 3);
                int bb = (nn * 16 + ((lane >> 4) << 3)) * 2;
                ldsm4t(sb + soff(WH_OFF, rr, bb), Bh);
                ldsm4t(sb + soff(WL_OFF, rr, bb), Bl);
                mma16816(xw[2 * nn],     Ah, Bh[0], Bh[1]);
                mma16816(xw[2 * nn + 1], Ah, Bh[2], Bh[3]);
                mma16816(xw[2 * nn],     Ah, Bl[0], Bl[1]);
                mma16816(xw[2 * nn + 1], Ah, Bl[2], Bl[3]);
                mma16816(xw[2 * nn],     Al, Bh[0], Bh[1]);
                mma16816(xw[2 * nn + 1], Al, Bh[2], Bh[3]);
            }
        }
        __syncthreads();   // all warps done reading W

        // store XW hi/lo into the W region (rows are warp-private)
        #pragma unroll
        for (int j = 0; j < 16; ++j) {
            int nbyte = 2 * (8 * j + 2 * q4);
            *(uint32_t*)(smem + soff(WH_OFF, warp * 16 + g,     nbyte)) = bpack(xw[j][0], xw[j][1]);
            *(uint32_t*)(smem + soff(WL_OFF, warp * 16 + g,     nbyte)) = bpacklo(xw[j][0], xw[j][1]);
            *(uint32_t*)(smem + soff(WH_OFF, warp * 16 + g + 8, nbyte)) = bpack(xw[j][2], xw[j][3]);
            *(uint32_t*)(smem + soff(WL_OFF, warp * 16 + g + 8, nbyte)) = bpacklo(xw[j][2], xw[j][3]);
        }
        __syncwarp();
    }

    // ===== fused per 32-key tile, ONLY over tiles containing valid keys:
    //       GEMM2(32 keys) -> exp/mask -> partial GEMM3 (unnormalized) =====
    // Keys t >= len contribute exactly 0 to oa and sm; their only reference-side
    // effect is the 1e-8*sum_all denominator term, bounded <= 2e-5 relative.
    const int ntiles = (len + 31) >> 5;   // 1..8
    float oa[16][4];
    #pragma unroll
    for (int j = 0; j < 16; ++j) { oa[j][0] = oa[j][1] = oa[j][2] = oa[j][3] = 0.f; }
    float sa0 = 0.f, sm0 = 0.f, sa1 = 0.f, sm1 = 0.f;

    #pragma unroll 1
    for (int ti = 0; ti < ntiles; ++ti) {
        const int kb = ti * 32;
        float la[4][4];
        #pragma unroll
        for (int j = 0; j < 4; ++j) { la[j][0] = la[j][1] = la[j][2] = la[j][3] = 0.f; }

        // GEMM2 tile: L[16 x 32] = XW @ X[kb..kb+32]^T (4-acc rotation)
        #pragma unroll
        for (int kt = 0; kt < 8; ++kt) {
            uint32_t Ah[4], Al[4];
            {
                int row = warp * 16 + (lane & 15);
                int byt = kt * 32 + ((lane >> 4) << 4);
                ldsm4(sb + soff(WH_OFF, row, byt), Ah);
                ldsm4(sb + soff(WL_OFF, row, byt), Al);
            }
            uint32_t B0h[4], B0l[4], B1h[4], B1l[4];
            int rrb = (lane & 7) + ((lane >> 4) << 3);
            int bb = kt * 32 + (((lane >> 3) & 1) << 4);
            ldsm4(sb + soff(XH_OFF, kb + rrb, bb), B0h);
            ldsm4(sb + soff(XL_OFF, kb + rrb, bb), B0l);
            ldsm4(sb + soff(XH_OFF, kb + 16 + rrb, bb), B1h);
            ldsm4(sb + soff(XL_OFF, kb + 16 + rrb, bb), B1l);
            mma16816(la[0], Ah, B0h[0], B0h[1]);
            mma16816(la[1], Ah, B0h[2], B0h[3]);
            mma16816(la[2], Ah, B1h[0], B1h[1]);
            mma16816(la[3], Ah, B1h[2], B1h[3]);
            mma16816(la[0], Ah, B0l[0], B0l[1]);
            mma16816(la[1], Ah, B0l[2], B0l[3]);
            mma16816(la[2], Ah, B1l[0], B1l[1]);
            mma16816(la[3], Ah, B1l[2], B1l[3]);
            mma16816(la[0], Al, B0h[0], B0h[1]);
            mma16816(la[1], Al, B0h[2], B0h[3]);
            mma16816(la[2], Al, B1h[0], B1h[1]);
            mma16816(la[3], Al, B1h[2], B1h[3]);
        }

        // tanh -> exp -> mask (unnormalized; row sums accumulated)
        #pragma unroll
        for (int j = 0; j < 4; ++j) {
            int tb = kb + 8 * j + 2 * q4;
            #pragma unroll
            for (int c = 0; c < 2; ++c) {
                const bool m = (tb + c) < len;
                {
                    float l = la[j][c];
                    float u = __expf(2.f * l);
                    float t2 = 1.f - __fdividef(2.f, u + 1.f);
                    float w = __expf(t2);
                    float wm = m ? w : 0.f;
                    sa0 += w; sm0 += wm; la[j][c] = wm;
                }
                {
                    float l = la[j][2 + c];
                    float u = __expf(2.f * l);
                    float t2 = 1.f - __fdividef(2.f, u + 1.f);
                    float w = __expf(t2);
                    float wm = m ? w : 0.f;
                    sa1 += w; sm1 += wm; la[j][2 + c] = wm;
                }
            }
        }

        // GEMM3 partial: oa += w_tile @ X[kb..kb+32] (two 16-key halves)
        #pragma unroll
        for (int h = 0; h < 2; ++h) {
            uint32_t ph[4], pl[4];
            ph[0] = bpack(la[2 * h][0], la[2 * h][1]);
            ph[1] = bpack(la[2 * h][2], la[2 * h][3]);
            ph[2] = bpack(la[2 * h + 1][0], la[2 * h + 1][1]);
            ph[3] = bpack(la[2 * h + 1][2], la[2 * h + 1][3]);
            pl[0] = bpacklo(la[2 * h][0], la[2 * h][1]);
            pl[1] = bpacklo(la[2 * h][2], la[2 * h][3]);
            pl[2] = bpacklo(la[2 * h + 1][0], la[2 * h + 1][1]);
            pl[3] = bpacklo(la[2 * h + 1][2], la[2 * h + 1][3]);
            #pragma unroll
            for (int nn = 0; nn < 8; ++nn) {
                uint32_t Bh[4], Bl[4];
                int rr = kb + h * 16 + (lane & 7) + (((lane >> 3) & 1) << 3);
                int bb = (nn * 16 + ((lane >> 4) << 3)) * 2;
                ldsm4t(sb + soff(XH_OFF, rr, bb), Bh);
                ldsm4t(sb + soff(XL_OFF, rr, bb), Bl);
                mma16816(oa[2 * nn],     ph, Bh[0], Bh[1]);
                mma16816(oa[2 * nn + 1], ph, Bh[2], Bh[3]);
                mma16816(oa[2 * nn],     ph, Bl[0], Bl[1]);
                mma16816(oa[2 * nn + 1], ph, Bl[2], Bl[3]);
                mma16816(oa[2 * nn],     pl, Bh[0], Bh[1]);
                mma16816(oa[2 * nn + 1], pl, Bh[2], Bh[3]);
            }
        }
    }

    // ===== row sums -> inverse -> scale -> store =====
    #pragma unroll
    for (int off = 1; off <= 2; off <<= 1) {
        sa0 += __shfl_xor_sync(0xffffffffu, sa0, off);
        sm0 += __shfl_xor_sync(0xffffffffu, sm0, off);
        sa1 += __shfl_xor_sync(0xffffffffu, sa1, off);
        sm1 += __shfl_xor_sync(0xffffffffu, sm1, off);
    }
    const float inv0 = 1.f / (sm0 + 1e-8f * sa0);
    const float inv1 = 1.f / (sm1 + 1e-8f * sa1);

    {
        const size_t rbase = (size_t)sent * 256 + r0;
        #pragma unroll
        for (int j = 0; j < 16; ++j) {
            int col = 8 * j + 2 * q4;
            float2 v0; v0.x = oa[j][0] * inv0; v0.y = oa[j][1] * inv0;
            float2 v1; v1.x = oa[j][2] * inv1; v1.y = oa[j][3] * inv1;
            *(float2*)(out + (rbase + g) * 128 + col) = v0;
            *(float2*)(out + (rbase + g + 8) * 128 + col) = v1;
        }
    }
}

extern "C" void kernel_launch(void* const* d_in, const int* in_sizes, int n_in,
                              void* d_out, int out_size)
{
    const float* words = (const float*)d_in[0];
    const float* Wm    = (const float*)d_in[1];
    const int*   vlen  = (const int*)d_in[2];
    float* out = (float*)d_out;

    cudaFuncSetAttribute(sattn_mma_kernel,
                         cudaFuncAttributeMaxDynamicSharedMemorySize, SMEM_TOTAL);
    sattn_mma_kernel<<<1024, 256, SMEM_TOTAL>>>(words, Wm, vlen, out);
}

// round 13
// speedup vs baseline: 1.5217x; 1.1628x over previous
#include <cuda_runtime.h>
#include <cuda_bf16.h>
#include <cstdint>

// smem: X hi/lo = 256x128 bf16 (row stride 256B, XOR-swizzled). W hi/lo = 128x128 bf16
// ([k][n]); after GEMM1 the W region is reused as XW hi/lo. During the prologue the
// other-half rows' XH/XL slots double as an fp32 cp.async staging area.
#define XH_OFF 0
#define XL_OFF 65536
#define WH_OFF 131072
#define WL_OFF 163840
#define SMEM_TOTAL 196608

__device__ __forceinline__ uint32_t smem_u32(const void* p) {
    uint32_t a;
    asm("{ .reg .u64 t; cvta.to.shared.u64 t, %1; cvt.u32.u64 %0, t; }" : "=r"(a) : "l"(p));
    return a;
}
__device__ __forceinline__ uint32_t soff(uint32_t region, int row, int byte) {
    return region + (uint32_t)(row * 256 + (byte ^ ((row & 7) << 4)));
}
__device__ __forceinline__ void ldsm4(uint32_t addr, uint32_t (&r)[4]) {
    asm volatile("ldmatrix.sync.aligned.m8n8.x4.shared.b16 {%0,%1,%2,%3}, [%4];"
                 : "=r"(r[0]), "=r"(r[1]), "=r"(r[2]), "=r"(r[3]) : "r"(addr));
}
__device__ __forceinline__ void ldsm4t(uint32_t addr, uint32_t (&r)[4]) {
    asm volatile("ldmatrix.sync.aligned.m8n8.x4.trans.shared.b16 {%0,%1,%2,%3}, [%4];"
                 : "=r"(r[0]), "=r"(r[1]), "=r"(r[2]), "=r"(r[3]) : "r"(addr));
}
__device__ __forceinline__ void mma16816(float (&c)[4], const uint32_t (&a)[4],
                                         uint32_t b0, uint32_t b1) {
    asm volatile("mma.sync.aligned.m16n8k16.row.col.f32.bf16.bf16.f32 "
                 "{%0,%1,%2,%3}, {%4,%5,%6,%7}, {%8,%9}, {%0,%1,%2,%3};"
                 : "+f"(c[0]), "+f"(c[1]), "+f"(c[2]), "+f"(c[3])
                 : "r"(a[0]), "r"(a[1]), "r"(a[2]), "r"(a[3]), "r"(b0), "r"(b1));
}
__device__ __forceinline__ uint32_t bpack(float x, float y) {
    __nv_bfloat162 h = __floats2bfloat162_rn(x, y);
    return *reinterpret_cast<uint32_t*>(&h);
}
__device__ __forceinline__ uint32_t bpacklo(float x, float y) {
    float hx = __bfloat162float(__float2bfloat16_rn(x));
    float hy = __bfloat162float(__float2bfloat16_rn(y));
    return bpack(x - hx, y - hy);
}
__device__ __forceinline__ void cpasync16(uint32_t dst, const void* src) {
    asm volatile("cp.async.cg.shared.global [%0], [%1], 16;"
                 :: "r"(dst), "l"(__cvta_generic_to_global(src)) : "memory");
}

__global__ void __launch_bounds__(256, 1)
sattn_mma_kernel(const float* __restrict__ words, const float* __restrict__ Wm,
                 const int* __restrict__ vlen, float* __restrict__ out)
{
    extern __shared__ __align__(1024) char smem[];
    const uint32_t sb = smem_u32(smem);
    const int tid = threadIdx.x, lane = tid & 31, warp = tid >> 5;
    const int sent = blockIdx.x >> 1, q0 = (blockIdx.x & 1) * 128;
    const int o0 = 128 - q0;                    // the other 128-row half
    const float* xg = words + (size_t)sent * 256 * 128;
    const int len = vlen[sent];
    const int g = lane >> 2, q4 = lane & 3;

    // ---- (1) async-stage the OTHER half's rows (fp32) into their own future
    //      XH/XL slots: rows o0..o0+63 -> XH side, o0+64..o0+127 -> XL side ----
    #pragma unroll
    for (int k = 0; k < 16; ++k) {
        int i = tid + (k << 8);                  // chunk 0..4095 (16B each)
        int ro = i >> 5, w = (i & 31) << 4;
        uint32_t dst = (ro < 64)
            ? (uint32_t)(XH_OFF + o0 * 256 + ro * 512 + w)
            : (uint32_t)(XL_OFF + o0 * 256 + (ro - 64) * 512 + w);
        cpasync16(sb + dst, (const char*)xg + (size_t)(o0 + ro) * 512 + w);
    }
    asm volatile("cp.async.commit_group;" ::: "memory");

    // ---- (2) classic load of OWN half rows [q0, q0+128) -> XH/XL ----
    #pragma unroll
    for (int k = 0; k < 16; ++k) {
        int i = tid + (k << 8);                  // 0..4095 float4 of own half
        int t = q0 + (i >> 5), b = (i & 31) << 3;
        float4 v = ((const float4*)xg)[(q0 << 5) + i];
        uint2 hw, lw;
        hw.x = bpack(v.x, v.y); hw.y = bpack(v.z, v.w);
        lw.x = bpacklo(v.x, v.y); lw.y = bpacklo(v.z, v.w);
        *(uint2*)(smem + soff(XH_OFF, t, b)) = hw;
        *(uint2*)(smem + soff(XL_OFF, t, b)) = lw;
    }
    // ---- (3) load W ([k][n]) -> WH/WL ----
    for (int i = tid; i < 4096; i += 256) {
        float4 v = ((const float4*)Wm)[i];
        int k = i >> 5, b = (i & 31) << 3;
        uint2 hw, lw;
        hw.x = bpack(v.x, v.y); hw.y = bpack(v.z, v.w);
        lw.x = bpacklo(v.x, v.y); lw.y = bpacklo(v.z, v.w);
        *(uint2*)(smem + soff(WH_OFF, k, b)) = hw;
        *(uint2*)(smem + soff(WL_OFF, k, b)) = lw;
    }
    __syncthreads();

    const int r0 = q0 + warp * 16;

    // ===== GEMM1: XW[16 x 128] = Xq @ W (3-pass split); X other-half streams in ====
    {
        float xw[16][4];
        #pragma unroll
        for (int j = 0; j < 16; ++j) { xw[j][0] = xw[j][1] = xw[j][2] = xw[j][3] = 0.f; }

        #pragma unroll
        for (int kt = 0; kt < 8; ++kt) {
            uint32_t Ah[4], Al[4];
            {
                int row = r0 + (lane & 15);
                int byt = kt * 32 + ((lane >> 4) << 4);
                ldsm4(sb + soff(XH_OFF, row, byt), Ah);
                ldsm4(sb + soff(XL_OFF, row, byt), Al);
            }
            #pragma unroll
            for (int nn = 0; nn < 8; ++nn) {
                uint32_t Bh[4], Bl[4];
                int rr = kt * 16 + (lane & 7) + (((lane >> 3) & 1) << 3);
                int bb = (nn * 16 + ((lane >> 4) << 3)) * 2;
                ldsm4t(sb + soff(WH_OFF, rr, bb), Bh);
                ldsm4t(sb + soff(WL_OFF, rr, bb), Bl);
                mma16816(xw[2 * nn],     Ah, Bh[0], Bh[1]);
                mma16816(xw[2 * nn + 1], Ah, Bh[2], Bh[3]);
                mma16816(xw[2 * nn],     Ah, Bl[0], Bl[1]);
                mma16816(xw[2 * nn + 1], Ah, Bl[2], Bl[3]);
                mma16816(xw[2 * nn],     Al, Bh[0], Bh[1]);
                mma16816(xw[2 * nn + 1], Al, Bh[2], Bh[3]);
            }
        }
        __syncthreads();   // all warps done reading W

        // store XW hi/lo into the W region (rows are warp-private)
        #pragma unroll
        for (int j = 0; j < 16; ++j) {
            int nbyte = 2 * (8 * j + 2 * q4);
            *(uint32_t*)(smem + soff(WH_OFF, warp * 16 + g,     nbyte)) = bpack(xw[j][0], xw[j][1]);
            *(uint32_t*)(smem + soff(WL_OFF, warp * 16 + g,     nbyte)) = bpacklo(xw[j][0], xw[j][1]);
            *(uint32_t*)(smem + soff(WH_OFF, warp * 16 + g + 8, nbyte)) = bpack(xw[j][2], xw[j][3]);
            *(uint32_t*)(smem + soff(WL_OFF, warp * 16 + g + 8, nbyte)) = bpacklo(xw[j][2], xw[j][3]);
        }
    }

    // ---- (4) finish staging: in-place convert other half fp32 -> hi/lo ----
    {
        asm volatile("cp.async.wait_group 0;" ::: "memory");
        float4 stg[16];
        #pragma unroll
        for (int k = 0; k < 16; ++k) {           // re-read exactly MY copied chunks
            int i = tid + (k << 8);
            int ro = i >> 5, w = (i & 31) << 4;
            uint32_t src = (ro < 64)
                ? (uint32_t)(XH_OFF + o0 * 256 + ro * 512 + w)
                : (uint32_t)(XL_OFF + o0 * 256 + (ro - 64) * 512 + w);
            stg[k] = *(const float4*)(smem + src);
        }
        __syncthreads();                          // all reads before any write
        #pragma unroll
        for (int k = 0; k < 16; ++k) {
            int i = tid + (k << 8);
            int r = o0 + (i >> 5), b = (i & 31) << 3;
            uint2 hw, lw;
            hw.x = bpack(stg[k].x, stg[k].y); hw.y = bpack(stg[k].z, stg[k].w);
            lw.x = bpacklo(stg[k].x, stg[k].y); lw.y = bpacklo(stg[k].z, stg[k].w);
            *(uint2*)(smem + soff(XH_OFF, r, b)) = hw;
            *(uint2*)(smem + soff(XL_OFF, r, b)) = lw;
        }
        __syncthreads();                          // full X + XW visible
    }

    // ===== fused per-tile loop over valid keys: 32-key tiles + optional 16-key tail
    const int rem = len & 31;
    const int n32 = (len >> 5) + (rem > 16 ? 1 : 0);
    const bool t16 = (rem >= 1 && rem <= 16);
    float oa[16][4];
    #pragma unroll
    for (int j = 0; j < 16; ++j) { oa[j][0] = oa[j][1] = oa[j][2] = oa[j][3] = 0.f; }
    float sa0 = 0.f, sm0 = 0.f, sa1 = 0.f, sm1 = 0.f;

    #pragma unroll 1
    for (int ti = 0; ti < n32; ++ti) {
        const int kb = ti * 32;
        float la[4][4];
        #pragma unroll
        for (int j = 0; j < 4; ++j) { la[j][0] = la[j][1] = la[j][2] = la[j][3] = 0.f; }

        #pragma unroll
        for (int kt = 0; kt < 8; ++kt) {
            uint32_t Ah[4], Al[4];
            {
                int row = warp * 16 + (lane & 15);
                int byt = kt * 32 + ((lane >> 4) << 4);
                ldsm4(sb + soff(WH_OFF, row, byt), Ah);
                ldsm4(sb + soff(WL_OFF, row, byt), Al);
            }
            uint32_t B0h[4], B0l[4], B1h[4], B1l[4];
            int rrb = (lane & 7) + ((lane >> 4) << 3);
            int bb = kt * 32 + (((lane >> 3) & 1) << 4);
            ldsm4(sb + soff(XH_OFF, kb + rrb, bb), B0h);
            ldsm4(sb + soff(XL_OFF, kb + rrb, bb), B0l);
            ldsm4(sb + soff(XH_OFF, kb + 16 + rrb, bb), B1h);
            ldsm4(sb + soff(XL_OFF, kb + 16 + rrb, bb), B1l);
            mma16816(la[0], Ah, B0h[0], B0h[1]);
            mma16816(la[1], Ah, B0h[2], B0h[3]);
            mma16816(la[2], Ah, B1h[0], B1h[1]);
            mma16816(la[3], Ah, B1h[2], B1h[3]);
            mma16816(la[0], Ah, B0l[0], B0l[1]);
            mma16816(la[1], Ah, B0l[2], B0l[3]);
            mma16816(la[2], Ah, B1l[0], B1l[1]);
            mma16816(la[3], Ah, B1l[2], B1l[3]);
            mma16816(la[0], Al, B0h[0], B0h[1]);
            mma16816(la[1], Al, B0h[2], B0h[3]);
            mma16816(la[2], Al, B1h[0], B1h[1]);
            mma16816(la[3], Al, B1h[2], B1h[3]);
        }

        #pragma unroll
        for (int j = 0; j < 4; ++j) {
            int tb = kb + 8 * j + 2 * q4;
            #pragma unroll
            for (int c = 0; c < 2; ++c) {
                const bool m = (tb + c) < len;
                {
                    float l = la[j][c];
                    float u = __expf(2.f * l);
                    float t2 = 1.f - __fdividef(2.f, u + 1.f);
                    float w = __expf(t2);
                    float wm = m ? w : 0.f;
                    sa0 += w; sm0 += wm; la[j][c] = wm;
                }
                {
                    float l = la[j][2 + c];
                    float u = __expf(2.f * l);
                    float t2 = 1.f - __fdividef(2.f, u + 1.f);
                    float w = __expf(t2);
                    float wm = m ? w : 0.f;
                    sa1 += w; sm1 += wm; la[j][2 + c] = wm;
                }
            }
        }

        #pragma unroll
        for (int h = 0; h < 2; ++h) {
            uint32_t ph[4], pl[4];
            ph[0] = bpack(la[2 * h][0], la[2 * h][1]);
            ph[1] = bpack(la[2 * h][2], la[2 * h][3]);
            ph[2] = bpack(la[2 * h + 1][0], la[2 * h + 1][1]);
            ph[3] = bpack(la[2 * h + 1][2], la[2 * h + 1][3]);
            pl[0] = bpacklo(la[2 * h][0], la[2 * h][1]);
            pl[1] = bpacklo(la[2 * h][2], la[2 * h][3]);
            pl[2] = bpacklo(la[2 * h + 1][0], la[2 * h + 1][1]);
            pl[3] = bpacklo(la[2 * h + 1][2], la[2 * h + 1][3]);
            #pragma unroll
            for (int nn = 0; nn < 8; ++nn) {
                uint32_t Bh[4], Bl[4];
                int rr = kb + h * 16 + (lane & 7) + (((lane >> 3) & 1) << 3);
                int bb = (nn * 16 + ((lane >> 4) << 3)) * 2;
                ldsm4t(sb + soff(XH_OFF, rr, bb), Bh);
                ldsm4t(sb + soff(XL_OFF, rr, bb), Bl);
                mma16816(oa[2 * nn],     ph, Bh[0], Bh[1]);
                mma16816(oa[2 * nn + 1], ph, Bh[2], Bh[3]);
                mma16816(oa[2 * nn],     ph, Bl[0], Bl[1]);
                mma16816(oa[2 * nn + 1], ph, Bl[2], Bl[3]);
                mma16816(oa[2 * nn],     pl, Bh[0], Bh[1]);
                mma16816(oa[2 * nn + 1], pl, Bh[2], Bh[3]);
            }
        }
    }

    // ---- 16-key tail tile (when len mod 32 in [1,16]) ----
    if (t16) {
        const int kb = n32 * 32;
        float la[2][4];
        la[0][0] = la[0][1] = la[0][2] = la[0][3] = 0.f;
        la[1][0] = la[1][1] = la[1][2] = la[1][3] = 0.f;

        #pragma unroll
        for (int kt = 0; kt < 8; ++kt) {
            uint32_t Ah[4], Al[4];
            {
                int row = warp * 16 + (lane & 15);
                int byt = kt * 32 + ((lane >> 4) << 4);
                ldsm4(sb + soff(WH_OFF, row, byt), Ah);
                ldsm4(sb + soff(WL_OFF, row, byt), Al);
            }
            uint32_t B0h[4], B0l[4];
            int rrb = (lane & 7) + ((lane >> 4) << 3);
            int bb = kt * 32 + (((lane >> 3) & 1) << 4);
            ldsm4(sb + soff(XH_OFF, kb + rrb, bb), B0h);
            ldsm4(sb + soff(XL_OFF, kb + rrb, bb), B0l);
            mma16816(la[0], Ah, B0h[0], B0h[1]);
            mma16816(la[1], Ah, B0h[2], B0h[3]);
            mma16816(la[0], Ah, B0l[0], B0l[1]);
            mma16816(la[1], Ah, B0l[2], B0l[3]);
            mma16816(la[0], Al, B0h[0], B0h[1]);
            mma16816(la[1], Al, B0h[2], B0h[3]);
        }

        #pragma unroll
        for (int j = 0; j < 2; ++j) {
            int tb = kb + 8 * j + 2 * q4;
            #pragma unroll
            for (int c = 0; c < 2; ++c) {
                const bool m = (tb + c) < len;
                {
                    float l = la[j][c];
                    float u = __expf(2.f * l);
                    float t2 = 1.f - __fdividef(2.f, u + 1.f);
                    float w = __expf(t2);
                    float wm = m ? w : 0.f;
                    sa0 += w; sm0 += wm; la[j][c] = wm;
                }
                {
                    float l = la[j][2 + c];
                    float u = __expf(2.f * l);
                    float t2 = 1.f - __fdividef(2.f, u + 1.f);
                    float w = __expf(t2);
                    float wm = m ? w : 0.f;
                    sa1 += w; sm1 += wm; la[j][2 + c] = wm;
                }
            }
        }

        uint32_t ph[4], pl[4];
        ph[0] = bpack(la[0][0], la[0][1]);
        ph[1] = bpack(la[0][2], la[0][3]);
        ph[2] = bpack(la[1][0], la[1][1]);
        ph[3] = bpack(la[1][2], la[1][3]);
        pl[0] = bpacklo(la[0][0], la[0][1]);
        pl[1] = bpacklo(la[0][2], la[0][3]);
        pl[2] = bpacklo(la[1][0], la[1][1]);
        pl[3] = bpacklo(la[1][2], la[1][3]);
        #pragma unroll
        for (int nn = 0; nn < 8; ++nn) {
            uint32_t Bh[4], Bl[4];
            int rr = kb + (lane & 7) + (((lane >> 3) & 1) << 3);
            int bb = (nn * 16 + ((lane >> 4) << 3)) * 2;
            ldsm4t(sb + soff(XH_OFF, rr, bb), Bh);
            ldsm4t(sb + soff(XL_OFF, rr, bb), Bl);
            mma16816(oa[2 * nn],     ph, Bh[0], Bh[1]);
            mma16816(oa[2 * nn + 1], ph, Bh[2], Bh[3]);
            mma16816(oa[2 * nn],     ph, Bl[0], Bl[1]);
            mma16816(oa[2 * nn + 1], ph, Bl[2], Bl[3]);
            mma16816(oa[2 * nn],     pl, Bh[0], Bh[1]);
            mma16816(oa[2 * nn + 1], pl, Bh[2], Bh[3]);
        }
    }

    // ===== row sums -> inverse -> scale -> store =====
    #pragma unroll
    for (int off = 1; off <= 2; off <<= 1) {
        sa0 += __shfl_xor_sync(0xffffffffu, sa0, off);
        sm0 += __shfl_xor_sync(0xffffffffu, sm0, off);
        sa1 += __shfl_xor_sync(0xffffffffu, sa1, off);
        sm1 += __shfl_xor_sync(0xffffffffu, sm1, off);
    }
    const float inv0 = 1.f / (sm0 + 1e-8f * sa0);
    const float inv1 = 1.f / (sm1 + 1e-8f * sa1);

    {
        const size_t rbase = (size_t)sent * 256 + r0;
        #pragma unroll
        for (int j = 0; j < 16; ++j) {
            int col = 8 * j + 2 * q4;
            float2 v0; v0.x = oa[j][0] * inv0; v0.y = oa[j][1] * inv0;
            float2 v1; v1.x = oa[j][2] * inv1; v1.y = oa[j][3] * inv1;
            *(float2*)(out + (rbase + g) * 128 + col) = v0;
            *(float2*)(out + (rbase + g + 8) * 128 + col) = v1;
        }
    }
}

extern "C" void kernel_launch(void* const* d_in, const int* in_sizes, int n_in,
                              void* d_out, int out_size)
{
    const float* words = (const float*)d_in[0];
    const float* Wm    = (const float*)d_in[1];
    const int*   vlen  = (const int*)d_in[2];
    float* out = (float*)d_out;

    cudaFuncSetAttribute(sattn_mma_kernel,
                         cudaFuncAttributeMaxDynamicSharedMemorySize, SMEM_TOTAL);
    sattn_mma_kernel<<<1024, 256, SMEM_TOTAL>>>(words, Wm, vlen, out);
}

// round 14
// speedup vs baseline: 1.5501x; 1.0186x over previous
#include <cuda_runtime.h>
#include <cuda_bf16.h>
#include <cstdint>

// smem: X hi/lo = 256x128 bf16 (row stride 256B, XOR-swizzled). W hi/lo = 128x128 bf16
// ([k][n]). XW never touches smem: GEMM1 accumulators are relabeled in-register as
// GEMM2 A-fragments. During the prologue the other-half rows' XH/XL slots double as
// an fp32 cp.async staging area.
#define XH_OFF 0
#define XL_OFF 65536
#define WH_OFF 131072
#define WL_OFF 163840
#define SMEM_TOTAL 196608

__device__ __forceinline__ uint32_t smem_u32(const void* p) {
    uint32_t a;
    asm("{ .reg .u64 t; cvta.to.shared.u64 t, %1; cvt.u32.u64 %0, t; }" : "=r"(a) : "l"(p));
    return a;
}
__device__ __forceinline__ uint32_t soff(uint32_t region, int row, int byte) {
    return region + (uint32_t)(row * 256 + (byte ^ ((row & 7) << 4)));
}
__device__ __forceinline__ void ldsm4(uint32_t addr, uint32_t (&r)[4]) {
    asm volatile("ldmatrix.sync.aligned.m8n8.x4.shared.b16 {%0,%1,%2,%3}, [%4];"
                 : "=r"(r[0]), "=r"(r[1]), "=r"(r[2]), "=r"(r[3]) : "r"(addr));
}
__device__ __forceinline__ void ldsm4t(uint32_t addr, uint32_t (&r)[4]) {
    asm volatile("ldmatrix.sync.aligned.m8n8.x4.trans.shared.b16 {%0,%1,%2,%3}, [%4];"
                 : "=r"(r[0]), "=r"(r[1]), "=r"(r[2]), "=r"(r[3]) : "r"(addr));
}
__device__ __forceinline__ void mma16816(float (&c)[4], const uint32_t (&a)[4],
                                         uint32_t b0, uint32_t b1) {
    asm volatile("mma.sync.aligned.m16n8k16.row.col.f32.bf16.bf16.f32 "
                 "{%0,%1,%2,%3}, {%4,%5,%6,%7}, {%8,%9}, {%0,%1,%2,%3};"
                 : "+f"(c[0]), "+f"(c[1]), "+f"(c[2]), "+f"(c[3])
                 : "r"(a[0]), "r"(a[1]), "r"(a[2]), "r"(a[3]), "r"(b0), "r"(b1));
}
__device__ __forceinline__ uint32_t bpack(float x, float y) {
    __nv_bfloat162 h = __floats2bfloat162_rn(x, y);
    return *reinterpret_cast<uint32_t*>(&h);
}
__device__ __forceinline__ uint32_t bpacklo(float x, float y) {
    float hx = __bfloat162float(__float2bfloat16_rn(x));
    float hy = __bfloat162float(__float2bfloat16_rn(y));
    return bpack(x - hx, y - hy);
}
__device__ __forceinline__ void cpasync16(uint32_t dst, const void* src) {
    asm volatile("cp.async.cg.shared.global [%0], [%1], 16;"
                 :: "r"(dst), "l"(__cvta_generic_to_global(src)) : "memory");
}

__global__ void __launch_bounds__(256, 1)
sattn_mma_kernel(const float* __restrict__ words, const float* __restrict__ Wm,
                 const int* __restrict__ vlen, float* __restrict__ out)
{
    extern __shared__ __align__(1024) char smem[];
    const uint32_t sb = smem_u32(smem);
    const int tid = threadIdx.x, lane = tid & 31, warp = tid >> 5;
    const int sent = blockIdx.x >> 1, q0 = (blockIdx.x & 1) * 128;
    const int o0 = 128 - q0;                    // the other 128-row half
    const float* xg = words + (size_t)sent * 256 * 128;
    const int len = vlen[sent];
    const int g = lane >> 2, q4 = lane & 3;

    // ---- (1) async-stage the OTHER half's rows (fp32) into their own future
    //      XH/XL slots: rows o0..o0+63 -> XH side, o0+64..o0+127 -> XL side ----
    #pragma unroll
    for (int k = 0; k < 16; ++k) {
        int i = tid + (k << 8);                  // chunk 0..4095 (16B each)
        int ro = i >> 5, w = (i & 31) << 4;
        uint32_t dst = (ro < 64)
            ? (uint32_t)(XH_OFF + o0 * 256 + ro * 512 + w)
            : (uint32_t)(XL_OFF + o0 * 256 + (ro - 64) * 512 + w);
        cpasync16(sb + dst, (const char*)xg + (size_t)(o0 + ro) * 512 + w);
    }
    asm volatile("cp.async.commit_group;" ::: "memory");

    // ---- (2) classic load of OWN half rows [q0, q0+128) -> XH/XL ----
    #pragma unroll
    for (int k = 0; k < 16; ++k) {
        int i = tid + (k << 8);                  // 0..4095 float4 of own half
        int t = q0 + (i >> 5), b = (i & 31) << 3;
        float4 v = ((const float4*)xg)[(q0 << 5) + i];
        uint2 hw, lw;
        hw.x = bpack(v.x, v.y); hw.y = bpack(v.z, v.w);
        lw.x = bpacklo(v.x, v.y); lw.y = bpacklo(v.z, v.w);
        *(uint2*)(smem + soff(XH_OFF, t, b)) = hw;
        *(uint2*)(smem + soff(XL_OFF, t, b)) = lw;
    }
    // ---- (3) load W ([k][n]) -> WH/WL ----
    for (int i = tid; i < 4096; i += 256) {
        float4 v = ((const float4*)Wm)[i];
        int k = i >> 5, b = (i & 31) << 3;
        uint2 hw, lw;
        hw.x = bpack(v.x, v.y); hw.y = bpack(v.z, v.w);
        lw.x = bpacklo(v.x, v.y); lw.y = bpacklo(v.z, v.w);
        *(uint2*)(smem + soff(WH_OFF, k, b)) = hw;
        *(uint2*)(smem + soff(WL_OFF, k, b)) = lw;
    }
    __syncthreads();

    const int r0 = q0 + warp * 16;

    // ===== GEMM1: XW[16 x 128] = Xq @ W (3-pass split); result stays in registers ====
    uint32_t ah[8][4], al[8][4];    // XW as GEMM2 A-fragments (hi/lo)
    {
        float xw[16][4];
        #pragma unroll
        for (int j = 0; j < 16; ++j) { xw[j][0] = xw[j][1] = xw[j][2] = xw[j][3] = 0.f; }

        #pragma unroll
        for (int kt = 0; kt < 8; ++kt) {
            uint32_t Ah[4], Al[4];
            {
                int row = r0 + (lane & 15);
                int byt = kt * 32 + ((lane >> 4) << 4);
                ldsm4(sb + soff(XH_OFF, row, byt), Ah);
                ldsm4(sb + soff(XL_OFF, row, byt), Al);
            }
            #pragma unroll
            for (int nn = 0; nn < 8; ++nn) {
                uint32_t Bh[4], Bl[4];
                int rr = kt * 16 + (lane & 7) + (((lane >> 3) & 1) << 3);
                int bb = (nn * 16 + ((lane >> 4) << 3)) * 2;
                ldsm4t(sb + soff(WH_OFF, rr, bb), Bh);
                ldsm4t(sb + soff(WL_OFF, rr, bb), Bl);
                mma16816(xw[2 * nn],     Ah, Bh[0], Bh[1]);
                mma16816(xw[2 * nn + 1], Ah, Bh[2], Bh[3]);
                mma16816(xw[2 * nn],     Ah, Bl[0], Bl[1]);
                mma16816(xw[2 * nn + 1], Ah, Bl[2], Bl[3]);
                mma16816(xw[2 * nn],     Al, Bh[0], Bh[1]);
                mma16816(xw[2 * nn + 1], Al, Bh[2], Bh[3]);
            }
        }

        // ---- relabel: C-fragment of GEMM1 == A-fragment of GEMM2 (R4-verified) ----
        #pragma unroll
        for (int kt = 0; kt < 8; ++kt) {
            ah[kt][0] = bpack(xw[2 * kt][0], xw[2 * kt][1]);
            ah[kt][1] = bpack(xw[2 * kt][2], xw[2 * kt][3]);
            ah[kt][2] = bpack(xw[2 * kt + 1][0], xw[2 * kt + 1][1]);
            ah[kt][3] = bpack(xw[2 * kt + 1][2], xw[2 * kt + 1][3]);
            al[kt][0] = bpacklo(xw[2 * kt][0], xw[2 * kt][1]);
            al[kt][1] = bpacklo(xw[2 * kt][2], xw[2 * kt][3]);
            al[kt][2] = bpacklo(xw[2 * kt + 1][0], xw[2 * kt + 1][1]);
            al[kt][3] = bpacklo(xw[2 * kt + 1][2], xw[2 * kt + 1][3]);
        }
    }

    // ---- (4) finish staging: in-place convert other half fp32 -> hi/lo ----
    {
        asm volatile("cp.async.wait_group 0;" ::: "memory");
        float4 stg[16];
        #pragma unroll
        for (int k = 0; k < 16; ++k) {           // re-read exactly MY copied chunks
            int i = tid + (k << 8);
            int ro = i >> 5, w = (i & 31) << 4;
            uint32_t src = (ro < 64)
                ? (uint32_t)(XH_OFF + o0 * 256 + ro * 512 + w)
                : (uint32_t)(XL_OFF + o0 * 256 + (ro - 64) * 512 + w);
            stg[k] = *(const float4*)(smem + src);
        }
        __syncthreads();                          // all reads before any write
        #pragma unroll
        for (int k = 0; k < 16; ++k) {
            int i = tid + (k << 8);
            int r = o0 + (i >> 5), b = (i & 31) << 3;
            uint2 hw, lw;
            hw.x = bpack(stg[k].x, stg[k].y); hw.y = bpack(stg[k].z, stg[k].w);
            lw.x = bpacklo(stg[k].x, stg[k].y); lw.y = bpacklo(stg[k].z, stg[k].w);
            *(uint2*)(smem + soff(XH_OFF, r, b)) = hw;
            *(uint2*)(smem + soff(XL_OFF, r, b)) = lw;
        }
        __syncthreads();                          // full X visible
    }

    // ===== fused per-tile loop over valid keys: 32-key tiles + optional 16-key tail
    const int rem = len & 31;
    const int n32 = (len >> 5) + (rem > 16 ? 1 : 0);
    const bool t16 = (rem >= 1 && rem <= 16);
    float oa[16][4];
    #pragma unroll
    for (int j = 0; j < 16; ++j) { oa[j][0] = oa[j][1] = oa[j][2] = oa[j][3] = 0.f; }
    float sa0 = 0.f, sm0 = 0.f, sa1 = 0.f, sm1 = 0.f;

    #pragma unroll 1
    for (int ti = 0; ti < n32; ++ti) {
        const int kb = ti * 32;
        float la[4][4];
        #pragma unroll
        for (int j = 0; j < 4; ++j) { la[j][0] = la[j][1] = la[j][2] = la[j][3] = 0.f; }

        // GEMM2 tile: L[16 x 32] = XW @ X[kb..kb+32]^T (A from registers)
        #pragma unroll
        for (int kt = 0; kt < 8; ++kt) {
            uint32_t B0h[4], B0l[4], B1h[4], B1l[4];
            int rrb = (lane & 7) + ((lane >> 4) << 3);
            int bb = kt * 32 + (((lane >> 3) & 1) << 4);
            ldsm4(sb + soff(XH_OFF, kb + rrb, bb), B0h);
            ldsm4(sb + soff(XL_OFF, kb + rrb, bb), B0l);
            ldsm4(sb + soff(XH_OFF, kb + 16 + rrb, bb), B1h);
            ldsm4(sb + soff(XL_OFF, kb + 16 + rrb, bb), B1l);
            mma16816(la[0], ah[kt], B0h[0], B0h[1]);
            mma16816(la[1], ah[kt], B0h[2], B0h[3]);
            mma16816(la[2], ah[kt], B1h[0], B1h[1]);
            mma16816(la[3], ah[kt], B1h[2], B1h[3]);
            mma16816(la[0], ah[kt], B0l[0], B0l[1]);
            mma16816(la[1], ah[kt], B0l[2], B0l[3]);
            mma16816(la[2], ah[kt], B1l[0], B1l[1]);
            mma16816(la[3], ah[kt], B1l[2], B1l[3]);
            mma16816(la[0], al[kt], B0h[0], B0h[1]);
            mma16816(la[1], al[kt], B0h[2], B0h[3]);
            mma16816(la[2], al[kt], B1h[0], B1h[1]);
            mma16816(la[3], al[kt], B1h[2], B1h[3]);
        }

        // tanh -> exp -> mask (unnormalized; row sums accumulated)
        #pragma unroll
        for (int j = 0; j < 4; ++j) {
            int tb = kb + 8 * j + 2 * q4;
            #pragma unroll
            for (int c = 0; c < 2; ++c) {
                const bool m = (tb + c) < len;
                {
                    float l = la[j][c];
                    float u = __expf(2.f * l);
                    float t2 = 1.f - __fdividef(2.f, u + 1.f);
                    float w = __expf(t2);
                    float wm = m ? w : 0.f;
                    sa0 += w; sm0 += wm; la[j][c] = wm;
                }
                {
                    float l = la[j][2 + c];
                    float u = __expf(2.f * l);
                    float t2 = 1.f - __fdividef(2.f, u + 1.f);
                    float w = __expf(t2);
                    float wm = m ? w : 0.f;
                    sa1 += w; sm1 += wm; la[j][2 + c] = wm;
                }
            }
        }

        // GEMM3 partial: oa += w_tile @ X[kb..kb+32] (two 16-key halves)
        #pragma unroll
        for (int h = 0; h < 2; ++h) {
            uint32_t ph[4], pl[4];
            ph[0] = bpack(la[2 * h][0], la[2 * h][1]);
            ph[1] = bpack(la[2 * h][2], la[2 * h][3]);
            ph[2] = bpack(la[2 * h + 1][0], la[2 * h + 1][1]);
            ph[3] = bpack(la[2 * h + 1][2], la[2 * h + 1][3]);
            pl[0] = bpacklo(la[2 * h][0], la[2 * h][1]);
            pl[1] = bpacklo(la[2 * h][2], la[2 * h][3]);
            pl[2] = bpacklo(la[2 * h + 1][0], la[2 * h + 1][1]);
            pl[3] = bpacklo(la[2 * h + 1][2], la[2 * h + 1][3]);
            #pragma unroll
            for (int nn = 0; nn < 8; ++nn) {
                uint32_t Bh[4], Bl[4];
                int rr = kb + h * 16 + (lane & 7) + (((lane >> 3) & 1) << 3);
                int bb = (nn * 16 + ((lane >> 4) << 3)) * 2;
                ldsm4t(sb + soff(XH_OFF, rr, bb), Bh);
                ldsm4t(sb + soff(XL_OFF, rr, bb), Bl);
                mma16816(oa[2 * nn],     ph, Bh[0], Bh[1]);
                mma16816(oa[2 * nn + 1], ph, Bh[2], Bh[3]);
                mma16816(oa[2 * nn],     ph, Bl[0], Bl[1]);
                mma16816(oa[2 * nn + 1], ph, Bl[2], Bl[3]);
                mma16816(oa[2 * nn],     pl, Bh[0], Bh[1]);
                mma16816(oa[2 * nn + 1], pl, Bh[2], Bh[3]);
            }
        }
    }

    // ---- 16-key tail tile (when len mod 32 in [1,16]) ----
    if (t16) {
        const int kb = n32 * 32;
        float la[2][4];
        la[0][0] = la[0][1] = la[0][2] = la[0][3] = 0.f;
        la[1][0] = la[1][1] = la[1][2] = la[1][3] = 0.f;

        #pragma unroll
        for (int kt = 0; kt < 8; ++kt) {
            uint32_t B0h[4], B0l[4];
            int rrb = (lane & 7) + ((lane >> 4) << 3);
            int bb = kt * 32 + (((lane >> 3) & 1) << 4);
            ldsm4(sb + soff(XH_OFF, kb + rrb, bb), B0h);
            ldsm4(sb + soff(XL_OFF, kb + rrb, bb), B0l);
            mma16816(la[0], ah[kt], B0h[0], B0h[1]);
            mma16816(la[1], ah[kt], B0h[2], B0h[3]);
            mma16816(la[0], ah[kt], B0l[0], B0l[1]);
            mma16816(la[1], ah[kt], B0l[2], B0l[3]);
            mma16816(la[0], al[kt], B0h[0], B0h[1]);
            mma16816(la[1], al[kt], B0h[2], B0h[3]);
        }

        #pragma unroll
        for (int j = 0; j < 2; ++j) {
            int tb = kb + 8 * j + 2 * q4;
            #pragma unroll
            for (int c = 0; c < 2; ++c) {
                const bool m = (tb + c) < len;
                {
                    float l = la[j][c];
                    float u = __expf(2.f * l);
                    float t2 = 1.f - __fdividef(2.f, u + 1.f);
                    float w = __expf(t2);
                    float wm = m ? w : 0.f;
                    sa0 += w; sm0 += wm; la[j][c] = wm;
                }
                {
                    float l = la[j][2 + c];
                    float u = __expf(2.f * l);
                    float t2 = 1.f - __fdividef(2.f, u + 1.f);
                    float w = __expf(t2);
                    float wm = m ? w : 0.f;
                    sa1 += w; sm1 += wm; la[j][2 + c] = wm;
                }
            }
        }

        uint32_t ph[4], pl[4];
        ph[0] = bpack(la[0][0], la[0][1]);
        ph[1] = bpack(la[0][2], la[0][3]);
        ph[2] = bpack(la[1][0], la[1][1]);
        ph[3] = bpack(la[1][2], la[1][3]);
        pl[0] = bpacklo(la[0][0], la[0][1]);
        pl[1] = bpacklo(la[0][2], la[0][3]);
        pl[2] = bpacklo(la[1][0], la[1][1]);
        pl[3] = bpacklo(la[1][2], la[1][3]);
        #pragma unroll
        for (int nn = 0; nn < 8; ++nn) {
            uint32_t Bh[4], Bl[4];
            int rr = kb + (lane & 7) + (((lane >> 3) & 1) << 3);
            int bb = (nn * 16 + ((lane >> 4) << 3)) * 2;
            ldsm4t(sb + soff(XH_OFF, rr, bb), Bh);
            ldsm4t(sb + soff(XL_OFF, rr, bb), Bl);
            mma16816(oa[2 * nn],     ph, Bh[0], Bh[1]);
            mma16816(oa[2 * nn + 1], ph, Bh[2], Bh[3]);
            mma16816(oa[2 * nn],     ph, Bl[0], Bl[1]);
            mma16816(oa[2 * nn + 1], ph, Bl[2], Bl[3]);
            mma16816(oa[2 * nn],     pl, Bh[0], Bh[1]);
            mma16816(oa[2 * nn + 1], pl, Bh[2], Bh[3]);
        }
    }

    // ===== row sums -> inverse -> scale -> store =====
    #pragma unroll
    for (int off = 1; off <= 2; off <<= 1) {
        sa0 += __shfl_xor_sync(0xffffffffu, sa0, off);
        sm0 += __shfl_xor_sync(0xffffffffu, sm0, off);
        sa1 += __shfl_xor_sync(0xffffffffu, sa1, off);
        sm1 += __shfl_xor_sync(0xffffffffu, sm1, off);
    }
    const float inv0 = 1.f / (sm0 + 1e-8f * sa0);
    const float inv1 = 1.f / (sm1 + 1e-8f * sa1);

    {
        const size_t rbase = (size_t)sent * 256 + r0;
        #pragma unroll
        for (int j = 0; j < 16; ++j) {
            int col = 8 * j + 2 * q4;
            float2 v0; v0.x = oa[j][0] * inv0; v0.y = oa[j][1] * inv0;
            float2 v1; v1.x = oa[j][2] * inv1; v1.y = oa[j][3] * inv1;
            *(float2*)(out + (rbase + g) * 128 + col) = v0;
            *(float2*)(out + (rbase + g + 8) * 128 + col) = v1;
        }
    }
}

extern "C" void kernel_launch(void* const* d_in, const int* in_sizes, int n_in,
                              void* d_out, int out_size)
{
    const float* words = (const float*)d_in[0];
    const float* Wm    = (const float*)d_in[1];
    const int*   vlen  = (const int*)d_in[2];
    float* out = (float*)d_out;

    cudaFuncSetAttribute(sattn_mma_kernel,
                         cudaFuncAttributeMaxDynamicSharedMemorySize, SMEM_TOTAL);
    sattn_mma_kernel<<<1024, 256, SMEM_TOTAL>>>(words, Wm, vlen, out);
}

// round 15
// speedup vs baseline: 1.9111x; 1.2329x over previous
#include <cuda_runtime.h>
#include <cuda_fp16.h>
#include <cstdint>

// smem: X hi/lo = 256x128 fp16 (row stride 256B, XOR-swizzled). W hi/lo = 128x128 fp16
// ([k][n]). XW never touches smem (register relabel). Prologue stages the other-half
// rows fp32 via cp.async into their own future XH/XL slots.
#define XH_OFF 0
#define XL_OFF 65536
#define WH_OFF 131072
#define WL_OFF 163840
#define SMEM_TOTAL 196608

__device__ __forceinline__ uint32_t smem_u32(const void* p) {
    uint32_t a;
    asm("{ .reg .u64 t; cvta.to.shared.u64 t, %1; cvt.u32.u64 %0, t; }" : "=r"(a) : "l"(p));
    return a;
}
__device__ __forceinline__ uint32_t soff(uint32_t region, int row, int byte) {
    return region + (uint32_t)(row * 256 + (byte ^ ((row & 7) << 4)));
}
__device__ __forceinline__ void ldsm4(uint32_t addr, uint32_t (&r)[4]) {
    asm volatile("ldmatrix.sync.aligned.m8n8.x4.shared.b16 {%0,%1,%2,%3}, [%4];"
                 : "=r"(r[0]), "=r"(r[1]), "=r"(r[2]), "=r"(r[3]) : "r"(addr));
}
__device__ __forceinline__ void ldsm4t(uint32_t addr, uint32_t (&r)[4]) {
    asm volatile("ldmatrix.sync.aligned.m8n8.x4.trans.shared.b16 {%0,%1,%2,%3}, [%4];"
                 : "=r"(r[0]), "=r"(r[1]), "=r"(r[2]), "=r"(r[3]) : "r"(addr));
}
__device__ __forceinline__ void mma16816(float (&c)[4], const uint32_t (&a)[4],
                                         uint32_t b0, uint32_t b1) {
    asm volatile("mma.sync.aligned.m16n8k16.row.col.f32.f16.f16.f32 "
                 "{%0,%1,%2,%3}, {%4,%5,%6,%7}, {%8,%9}, {%0,%1,%2,%3};"
                 : "+f"(c[0]), "+f"(c[1]), "+f"(c[2]), "+f"(c[3])
                 : "r"(a[0]), "r"(a[1]), "r"(a[2]), "r"(a[3]), "r"(b0), "r"(b1));
}
__device__ __forceinline__ uint32_t hpack(float x, float y) {
    __half2 h = __floats2half2_rn(x, y);
    return *reinterpret_cast<uint32_t*>(&h);
}
__device__ __forceinline__ uint32_t hpacklo(float x, float y) {
    float hx = __half2float(__float2half_rn(x));
    float hy = __half2float(__float2half_rn(y));
    return hpack(x - hx, y - hy);
}
__device__ __forceinline__ float tanh_fast(float x) {
    float r;
    asm("tanh.approx.f32 %0, %1;" : "=f"(r) : "f"(x));
    return r;
}
__device__ __forceinline__ void cpasync16(uint32_t dst, const void* src) {
    asm volatile("cp.async.cg.shared.global [%0], [%1], 16;"
                 :: "r"(dst), "l"(__cvta_generic_to_global(src)) : "memory");
}

__global__ void __launch_bounds__(256, 1)
sattn_mma_kernel(const float* __restrict__ words, const float* __restrict__ Wm,
                 const int* __restrict__ vlen, float* __restrict__ out)
{
    extern __shared__ __align__(1024) char smem[];
    const uint32_t sb = smem_u32(smem);
    const int tid = threadIdx.x, lane = tid & 31, warp = tid >> 5;
    const int sent = blockIdx.x >> 1, q0 = (blockIdx.x & 1) * 128;
    const int o0 = 128 - q0;                    // the other 128-row half
    const float* xg = words + (size_t)sent * 256 * 128;
    const int len = vlen[sent];
    const int g = lane >> 2, q4 = lane & 3;

    // ---- (1) async-stage the OTHER half's rows (fp32) ----
    #pragma unroll
    for (int k = 0; k < 16; ++k) {
        int i = tid + (k << 8);
        int ro = i >> 5, w = (i & 31) << 4;
        uint32_t dst = (ro < 64)
            ? (uint32_t)(XH_OFF + o0 * 256 + ro * 512 + w)
            : (uint32_t)(XL_OFF + o0 * 256 + (ro - 64) * 512 + w);
        cpasync16(sb + dst, (const char*)xg + (size_t)(o0 + ro) * 512 + w);
    }
    asm volatile("cp.async.commit_group;" ::: "memory");

    // ---- (2) classic load of OWN half rows [q0, q0+128) -> XH/XL ----
    #pragma unroll
    for (int k = 0; k < 16; ++k) {
        int i = tid + (k << 8);
        int t = q0 + (i >> 5), b = (i & 31) << 3;
        float4 v = ((const float4*)xg)[(q0 << 5) + i];
        uint2 hw, lw;
        hw.x = hpack(v.x, v.y); hw.y = hpack(v.z, v.w);
        lw.x = hpacklo(v.x, v.y); lw.y = hpacklo(v.z, v.w);
        *(uint2*)(smem + soff(XH_OFF, t, b)) = hw;
        *(uint2*)(smem + soff(XL_OFF, t, b)) = lw;
    }
    // ---- (3) load W ([k][n]) -> WH/WL ----
    for (int i = tid; i < 4096; i += 256) {
        float4 v = ((const float4*)Wm)[i];
        int k = i >> 5, b = (i & 31) << 3;
        uint2 hw, lw;
        hw.x = hpack(v.x, v.y); hw.y = hpack(v.z, v.w);
        lw.x = hpacklo(v.x, v.y); lw.y = hpacklo(v.z, v.w);
        *(uint2*)(smem + soff(WH_OFF, k, b)) = hw;
        *(uint2*)(smem + soff(WL_OFF, k, b)) = lw;
    }
    __syncthreads();

    const int r0 = q0 + warp * 16;

    // ===== GEMM1: XW[16 x 128] = Xq @ W (3-pass split); result stays in registers ====
    uint32_t ah[8][4], al[8][4];
    {
        float xw[16][4];
        #pragma unroll
        for (int j = 0; j < 16; ++j) { xw[j][0] = xw[j][1] = xw[j][2] = xw[j][3] = 0.f; }

        #pragma unroll
        for (int kt = 0; kt < 8; ++kt) {
            uint32_t Ah[4], Al[4];
            {
                int row = r0 + (lane & 15);
                int byt = kt * 32 + ((lane >> 4) << 4);
                ldsm4(sb + soff(XH_OFF, row, byt), Ah);
                ldsm4(sb + soff(XL_OFF, row, byt), Al);
            }
            #pragma unroll
            for (int nn = 0; nn < 8; ++nn) {
                uint32_t Bh[4], Bl[4];
                int rr = kt * 16 + (lane & 7) + (((lane >> 3) & 1) << 3);
                int bb = (nn * 16 + ((lane >> 4) << 3)) * 2;
                ldsm4t(sb + soff(WH_OFF, rr, bb), Bh);
                ldsm4t(sb + soff(WL_OFF, rr, bb), Bl);
                mma16816(xw[2 * nn],     Ah, Bh[0], Bh[1]);
                mma16816(xw[2 * nn + 1], Ah, Bh[2], Bh[3]);
                mma16816(xw[2 * nn],     Ah, Bl[0], Bl[1]);
                mma16816(xw[2 * nn + 1], Ah, Bl[2], Bl[3]);
                mma16816(xw[2 * nn],     Al, Bh[0], Bh[1]);
                mma16816(xw[2 * nn + 1], Al, Bh[2], Bh[3]);
            }
        }

        // relabel: C-fragment of GEMM1 == A-fragment of GEMM2
        #pragma unroll
        for (int kt = 0; kt < 8; ++kt) {
            ah[kt][0] = hpack(xw[2 * kt][0], xw[2 * kt][1]);
            ah[kt][1] = hpack(xw[2 * kt][2], xw[2 * kt][3]);
            ah[kt][2] = hpack(xw[2 * kt + 1][0], xw[2 * kt + 1][1]);
            ah[kt][3] = hpack(xw[2 * kt + 1][2], xw[2 * kt + 1][3]);
            al[kt][0] = hpacklo(xw[2 * kt][0], xw[2 * kt][1]);
            al[kt][1] = hpacklo(xw[2 * kt][2], xw[2 * kt][3]);
            al[kt][2] = hpacklo(xw[2 * kt + 1][0], xw[2 * kt + 1][1]);
            al[kt][3] = hpacklo(xw[2 * kt + 1][2], xw[2 * kt + 1][3]);
        }
    }

    // ---- (4) finish staging: in-place convert other half fp32 -> hi/lo ----
    {
        asm volatile("cp.async.wait_group 0;" ::: "memory");
        float4 stg[16];
        #pragma unroll
        for (int k = 0; k < 16; ++k) {
            int i = tid + (k << 8);
            int ro = i >> 5, w = (i & 31) << 4;
            uint32_t src = (ro < 64)
                ? (uint32_t)(XH_OFF + o0 * 256 + ro * 512 + w)
                : (uint32_t)(XL_OFF + o0 * 256 + (ro - 64) * 512 + w);
            stg[k] = *(const float4*)(smem + src);
        }
        __syncthreads();
        #pragma unroll
        for (int k = 0; k < 16; ++k) {
            int i = tid + (k << 8);
            int r = o0 + (i >> 5), b = (i & 31) << 3;
            uint2 hw, lw;
            hw.x = hpack(stg[k].x, stg[k].y); hw.y = hpack(stg[k].z, stg[k].w);
            lw.x = hpacklo(stg[k].x, stg[k].y); lw.y = hpacklo(stg[k].z, stg[k].w);
            *(uint2*)(smem + soff(XH_OFF, r, b)) = hw;
            *(uint2*)(smem + soff(XL_OFF, r, b)) = lw;
        }
        __syncthreads();
    }

    // ===== fused per-tile loop over valid keys: 32-key tiles + optional 16-key tail
    const int rem = len & 31;
    const int n32 = (len >> 5) + (rem > 16 ? 1 : 0);
    const bool t16 = (rem >= 1 && rem <= 16);
    float oa[16][4];
    #pragma unroll
    for (int j = 0; j < 16; ++j) { oa[j][0] = oa[j][1] = oa[j][2] = oa[j][3] = 0.f; }
    float sa0 = 0.f, sm0 = 0.f, sa1 = 0.f, sm1 = 0.f;

    #pragma unroll 1
    for (int ti = 0; ti < n32; ++ti) {
        const int kb = ti * 32;
        float la[4][4];
        #pragma unroll
        for (int j = 0; j < 4; ++j) { la[j][0] = la[j][1] = la[j][2] = la[j][3] = 0.f; }

        // GEMM2 tile: L[16 x 32] = XW @ X[kb..kb+32]^T (3-pass, A from registers)
        #pragma unroll
        for (int kt = 0; kt < 8; ++kt) {
            uint32_t B0h[4], B0l[4], B1h[4], B1l[4];
            int rrb = (lane & 7) + ((lane >> 4) << 3);
            int bb = kt * 32 + (((lane >> 3) & 1) << 4);
            ldsm4(sb + soff(XH_OFF, kb + rrb, bb), B0h);
            ldsm4(sb + soff(XL_OFF, kb + rrb, bb), B0l);
            ldsm4(sb + soff(XH_OFF, kb + 16 + rrb, bb), B1h);
            ldsm4(sb + soff(XL_OFF, kb + 16 + rrb, bb), B1l);
            mma16816(la[0], ah[kt], B0h[0], B0h[1]);
            mma16816(la[1], ah[kt], B0h[2], B0h[3]);
            mma16816(la[2], ah[kt], B1h[0], B1h[1]);
            mma16816(la[3], ah[kt], B1h[2], B1h[3]);
            mma16816(la[0], ah[kt], B0l[0], B0l[1]);
            mma16816(la[1], ah[kt], B0l[2], B0l[3]);
            mma16816(la[2], ah[kt], B1l[0], B1l[1]);
            mma16816(la[3], ah[kt], B1l[2], B1l[3]);
            mma16816(la[0], al[kt], B0h[0], B0h[1]);
            mma16816(la[1], al[kt], B0h[2], B0h[3]);
            mma16816(la[2], al[kt], B1h[0], B1h[1]);
            mma16816(la[3], al[kt], B1h[2], B1h[3]);
        }

        // tanh -> exp -> mask (tanh.approx + ex2; unnormalized; sums accumulated)
        #pragma unroll
        for (int j = 0; j < 4; ++j) {
            int tb = kb + 8 * j + 2 * q4;
            #pragma unroll
            for (int c = 0; c < 2; ++c) {
                const bool m = (tb + c) < len;
                {
                    float w = __expf(tanh_fast(la[j][c]));
                    float wm = m ? w : 0.f;
                    sa0 += w; sm0 += wm; la[j][c] = wm;
                }
                {
                    float w = __expf(tanh_fast(la[j][2 + c]));
                    float wm = m ? w : 0.f;
                    sa1 += w; sm1 += wm; la[j][2 + c] = wm;
                }
            }
        }

        // GEMM3 partial (single-pass fp16): oa += p_hi @ X_hi
        #pragma unroll
        for (int h = 0; h < 2; ++h) {
            uint32_t ph[4];
            ph[0] = hpack(la[2 * h][0], la[2 * h][1]);
            ph[1] = hpack(la[2 * h][2], la[2 * h][3]);
            ph[2] = hpack(la[2 * h + 1][0], la[2 * h + 1][1]);
            ph[3] = hpack(la[2 * h + 1][2], la[2 * h + 1][3]);
            #pragma unroll
            for (int nn = 0; nn < 8; ++nn) {
                uint32_t Bh[4];
                int rr = kb + h * 16 + (lane & 7) + (((lane >> 3) & 1) << 3);
                int bb = (nn * 16 + ((lane >> 4) << 3)) * 2;
                ldsm4t(sb + soff(XH_OFF, rr, bb), Bh);
                mma16816(oa[2 * nn],     ph, Bh[0], Bh[1]);
                mma16816(oa[2 * nn + 1], ph, Bh[2], Bh[3]);
            }
        }
    }

    // ---- 16-key tail tile (when len mod 32 in [1,16]) ----
    if (t16) {
        const int kb = n32 * 32;
        float la[2][4];
        la[0][0] = la[0][1] = la[0][2] = la[0][3] = 0.f;
        la[1][0] = la[1][1] = la[1][2] = la[1][3] = 0.f;

        #pragma unroll
        for (int kt = 0; kt < 8; ++kt) {
            uint32_t B0h[4], B0l[4];
            int rrb = (lane & 7) + ((lane >> 4) << 3);
            int bb = kt * 32 + (((lane >> 3) & 1) << 4);
            ldsm4(sb + soff(XH_OFF, kb + rrb, bb), B0h);
            ldsm4(sb + soff(XL_OFF, kb + rrb, bb), B0l);
            mma16816(la[0], ah[kt], B0h[0], B0h[1]);
            mma16816(la[1], ah[kt], B0h[2], B0h[3]);
            mma16816(la[0], ah[kt], B0l[0], B0l[1]);
            mma16816(la[1], ah[kt], B0l[2], B0l[3]);
            mma16816(la[0], al[kt], B0h[0], B0h[1]);
            mma16816(la[1], al[kt], B0h[2], B0h[3]);
        }

        #pragma unroll
        for (int j = 0; j < 2; ++j) {
            int tb = kb + 8 * j + 2 * q4;
            #pragma unroll
            for (int c = 0; c < 2; ++c) {
                const bool m = (tb + c) < len;
                {
                    float w = __expf(tanh_fast(la[j][c]));
                    float wm = m ? w : 0.f;
                    sa0 += w; sm0 += wm; la[j][c] = wm;
                }
                {
                    float w = __expf(tanh_fast(la[j][2 + c]));
                    float wm = m ? w : 0.f;
                    sa1 += w; sm1 += wm; la[j][2 + c] = wm;
                }
            }
        }

        uint32_t ph[4];
        ph[0] = hpack(la[0][0], la[0][1]);
        ph[1] = hpack(la[0][2], la[0][3]);
        ph[2] = hpack(la[1][0], la[1][1]);
        ph[3] = hpack(la[1][2], la[1][3]);
        #pragma unroll
        for (int nn = 0; nn < 8; ++nn) {
            uint32_t Bh[4];
            int rr = kb + (lane & 7) + (((lane >> 3) & 1) << 3);
            int bb = (nn * 16 + ((lane >> 4) << 3)) * 2;
            ldsm4t(sb + soff(XH_OFF, rr, bb), Bh);
            mma16816(oa[2 * nn],     ph, Bh[0], Bh[1]);
            mma16816(oa[2 * nn + 1], ph, Bh[2], Bh[3]);
        }
    }

    // ===== row sums -> inverse -> scale -> store =====
    #pragma unroll
    for (int off = 1; off <= 2; off <<= 1) {
        sa0 += __shfl_xor_sync(0xffffffffu, sa0, off);
        sm0 += __shfl_xor_sync(0xffffffffu, sm0, off);
        sa1 += __shfl_xor_sync(0xffffffffu, sa1, off);
        sm1 += __shfl_xor_sync(0xffffffffu, sm1, off);
    }
    const float inv0 = 1.f / (sm0 + 1e-8f * sa0);
    const float inv1 = 1.f / (sm1 + 1e-8f * sa1);

    {
        const size_t rbase = (size_t)sent * 256 + r0;
        #pragma unroll
        for (int j = 0; j < 16; ++j) {
            int col = 8 * j + 2 * q4;
            float2 v0; v0.x = oa[j][0] * inv0; v0.y = oa[j][1] * inv0;
            float2 v1; v1.x = oa[j][2] * inv1; v1.y = oa[j][3] * inv1;
            *(float2*)(out + (rbase + g) * 128 + col) = v0;
            *(float2*)(out + (rbase + g + 8) * 128 + col) = v1;
        }
    }
}

extern "C" void kernel_launch(void* const* d_in, const int* in_sizes, int n_in,
                              void* d_out, int out_size)
{
    const float* words = (const float*)d_in[0];
    const float* Wm    = (const float*)d_in[1];
    const int*   vlen  = (const int*)d_in[2];
    float* out = (float*)d_out;

    cudaFuncSetAttribute(sattn_mma_kernel,
                         cudaFuncAttributeMaxDynamicSharedMemorySize, SMEM_TOTAL);
    sattn_mma_kernel<<<1024, 256, SMEM_TOTAL>>>(words, Wm, vlen, out);
}